// round 3
// baseline (speedup 1.0000x reference)
#include <cuda_runtime.h>
#include <cstdint>

#define BATCH  32
#define CIN    64
#define COUT   8
#define HW     65536
#define KSTEPS 11

// Scratch (static __device__ — allocation-free per harness rules)
__device__ float4 g_feat0[(size_t)BATCH * HW];           // 32 MB: channels 0-3
__device__ float4 g_feat1[(size_t)BATCH * HW];           // 32 MB: channels 4-7
__device__ float  g_scope[(size_t)BATCH * HW];           // 8 MB: resident scope chain
__device__ unsigned long long g_slots[KSTEPS][BATCH];    // argmax slots per step

// -------------------------------------------------------------------------
__global__ void k_init_slots() {
    int t = threadIdx.x;
    if (t < KSTEPS * BATCH) ((unsigned long long*)g_slots)[t] = 0ull;
}

// Block-wide max of packed (value_bits<<32 | ~idx). Valid on thread 0.
__device__ __forceinline__ unsigned long long block_reduce_max(
        unsigned long long v, unsigned long long* sred) {
    #pragma unroll
    for (int s = 16; s > 0; s >>= 1) {
        unsigned long long o = __shfl_down_sync(0xFFFFFFFFu, v, s);
        if (o > v) v = o;
    }
    if ((threadIdx.x & 31) == 0) sred[threadIdx.x >> 5] = v;
    __syncthreads();
    if (threadIdx.x < 8) {
        v = sred[threadIdx.x];
        #pragma unroll
        for (int s = 4; s > 0; s >>= 1) {
            unsigned long long o = __shfl_down_sync(0x000000FFu, v, s);
            if (o > v) v = o;
        }
    }
    return v;
}

__device__ __forceinline__ unsigned long long pack_key(float key, int idx) {
    return ((unsigned long long)__float_as_uint(key) << 32)
         | (unsigned long long)(0xFFFFFFFFu - (unsigned)idx);
}

// -------------------------------------------------------------------------
// Kernel 0: feat = gate*(W@x + b) + coord grid; scopes[:,0]=1; scope=1;
// partial argmax of rand into slot 0.
// Grid: 2048 blocks x 256 threads, 4 consecutive pixels/thread (x coalesced).
__global__ void __launch_bounds__(256) k_feat(
        const float* __restrict__ x, const float* __restrict__ rnd,
        const float* __restrict__ w, const float* __restrict__ bias,
        const float* __restrict__ gate_p, float* __restrict__ out) {
    __shared__ float sw[CIN * COUT + COUT];
    __shared__ unsigned long long sred[8];
    int tid = threadIdx.x;
    for (int i = tid; i < CIN * COUT; i += 256) {
        int o = i / CIN, c = i % CIN;
        sw[c * COUT + o] = w[i];                 // transposed: [c][o]
    }
    if (tid < COUT) sw[CIN * COUT + tid] = bias[tid];
    __syncthreads();

    float gate = *gate_p;
    int b     = blockIdx.x >> 6;
    int pin   = (blockIdx.x & 63) * 1024 + tid * 4;   // pixel-in-batch
    const float4* x4 = (const float4*)x + ((size_t)b * CIN) * (HW / 4) + (pin >> 2);

    float acc[COUT][4];
    #pragma unroll
    for (int o = 0; o < COUT; o++) {
        float bv = sw[CIN * COUT + o];
        #pragma unroll
        for (int j = 0; j < 4; j++) acc[o][j] = bv;
    }

    #pragma unroll 8
    for (int c = 0; c < CIN; c++) {
        float4 v = __ldcs(&x4[(size_t)c * (HW / 4)]);   // x never re-read: stream
        float xv[4] = {v.x, v.y, v.z, v.w};
        #pragma unroll
        for (int o = 0; o < COUT; o++) {
            float wv = sw[c * COUT + o];
            #pragma unroll
            for (int j = 0; j < 4; j++) acc[o][j] = fmaf(wv, xv[j], acc[o][j]);
        }
    }

    const float step = 2.0f / 255.0f;
    #pragma unroll
    for (int j = 0; j < 4; j++) {
        int p  = pin + j;
        int h  = p >> 8;
        int wi = p & 255;
        float4 f0, f1;
        f0.x = gate * acc[0][j]; f0.y = gate * acc[1][j];
        f0.z = gate * acc[2][j]; f0.w = gate * acc[3][j];
        f1.x = gate * acc[4][j]; f1.y = gate * acc[5][j];
        f1.z = fmaf((float)h,  step, -1.0f) + gate * acc[6][j];
        f1.w = fmaf((float)wi, step, -1.0f) + gate * acc[7][j];
        size_t fb = (size_t)b * HW + p;
        g_feat0[fb] = f0;
        g_feat1[fb] = f1;
    }

    // scope = 1 (resident scratch, normal store); scopes[b,0,:] = 1 (write-through)
    float4 ones = make_float4(1.0f, 1.0f, 1.0f, 1.0f);
    *(float4*)&g_scope[(size_t)b * HW + pin] = ones;
    float* scopes = out + (size_t)BATCH * KSTEPS * HW;
    __stwt((float4*)&scopes[((size_t)b * KSTEPS) * HW + pin], ones);

    // argmax of rand (scope == 1) for step 0
    float4 rv = ((const float4*)rnd)[((size_t)b * HW + pin) >> 2];
    float rj[4] = {rv.x, rv.y, rv.z, rv.w};
    unsigned long long best = 0ull;
    #pragma unroll
    for (int j = 0; j < 4; j++) {
        unsigned long long pk = pack_key(rj[j], pin + j);
        if (pk > best) best = pk;
    }
    best = block_reduce_max(best, sred);
    if (tid == 0) atomicMax(&g_slots[0][b], best);
}

// -------------------------------------------------------------------------
// Step kernel k = 0..9: read seed from slot[k]; alpha; write masks[:,k],
// scopes[:,k+1] (write-through, never GPU-re-read); update resident g_scope;
// partial argmax into slot[k+1] (except k==9 -> masks[:,10] = final scope).
// Coalesced mapping: p = block_base + tid + 256*j.
__global__ void __launch_bounds__(256) k_step(
        const float* __restrict__ rnd, const float* __restrict__ lsig_p,
        float* __restrict__ out, int k) {
    __shared__ unsigned long long sred[8];
    int tid = threadIdx.x;
    int b   = blockIdx.x >> 6;
    int pin = (blockIdx.x & 63) * 1024 + tid;

    unsigned long long sl = g_slots[k][b];
    unsigned int idx = 0xFFFFFFFFu - (unsigned int)(sl & 0xFFFFFFFFull);
    size_t seedbase = (size_t)b * HW + idx;
    float4 s0 = g_feat0[seedbase];
    float4 s1 = g_feat1[seedbase];
    float neg_inv_sigma = -1.0f / expf(*lsig_p);

    float* masks  = out;
    float* scopes = out + (size_t)BATCH * KSTEPS * HW;
    float* scope_out = scopes + ((size_t)b * KSTEPS + k + 1) * HW;
    float* mask_out  = masks  + ((size_t)b * KSTEPS + k)     * HW;
    float* mask_last = masks  + ((size_t)b * KSTEPS + KSTEPS - 1) * HW;

    unsigned long long best = 0ull;
    #pragma unroll
    for (int j = 0; j < 4; j++) {
        int p = pin + 256 * j;
        size_t base = (size_t)b * HW + p;
        float  s  = g_scope[base];
        float  r  = rnd[base];
        float4 f0 = g_feat0[base];
        float4 f1 = g_feat1[base];
        float d = 0.0f, t;
        t = f0.x - s0.x; d = fmaf(t, t, d);
        t = f0.y - s0.y; d = fmaf(t, t, d);
        t = f0.z - s0.z; d = fmaf(t, t, d);
        t = f0.w - s0.w; d = fmaf(t, t, d);
        t = f1.x - s1.x; d = fmaf(t, t, d);
        t = f1.y - s1.y; d = fmaf(t, t, d);
        t = f1.z - s1.z; d = fmaf(t, t, d);
        t = f1.w - s1.w; d = fmaf(t, t, d);
        float a = expf(d * neg_inv_sigma);
        a = fminf(fmaxf(a, 0.01f), 0.99f);
        float m  = s * a;
        float ns = s * (1.0f - a);
        __stwt(&mask_out[p], m);            // output: write-through, no L2 alloc
        __stwt(&scope_out[p], ns);          // output: write-through, no L2 alloc
        g_scope[base] = ns;                 // resident chain: normal store
        if (k == KSTEPS - 2) {
            __stwt(&mask_last[p], ns);      // masks[:,10] = final scope
        } else {
            unsigned long long pk = pack_key(r * ns, p);
            if (pk > best) best = pk;
        }
    }

    if (k != KSTEPS - 2) {
        best = block_reduce_max(best, sred);
        if (tid == 0) atomicMax(&g_slots[k + 1][b], best);
    }
}

// -------------------------------------------------------------------------
extern "C" void kernel_launch(void* const* d_in, const int* in_sizes, int n_in,
                              void* d_out, int out_size) {
    const float* x    = (const float*)d_in[0];
    const float* rnd  = (const float*)d_in[1];
    const float* w    = (const float*)d_in[2];
    const float* bias = (const float*)d_in[3];
    const float* gate = (const float*)d_in[4];
    const float* lsig = (const float*)d_in[5];
    float* out = (float*)d_out;

    k_init_slots<<<1, KSTEPS * BATCH>>>();
    k_feat<<<BATCH * 64, 256>>>(x, rnd, w, bias, gate, out);
    for (int k = 0; k < KSTEPS - 1; k++)
        k_step<<<BATCH * 64, 256>>>(rnd, lsig, out, k);
}

// round 4
// speedup vs baseline: 1.0925x; 1.0925x over previous
#include <cuda_runtime.h>
#include <cstdint>

#define BATCH  32
#define CIN    64
#define COUT   8
#define HW     65536
#define KSTEPS 11

// Scratch (static __device__ — allocation-free per harness rules)
__device__ float4 g_feat0[(size_t)BATCH * HW];           // 32 MB: channels 0-3
__device__ float4 g_feat1[(size_t)BATCH * HW];           // 32 MB: channels 4-7
__device__ unsigned long long g_slots[KSTEPS][BATCH];    // argmax slots per step

// -------------------------------------------------------------------------
__global__ void k_init_slots() {
    int t = threadIdx.x;
    if (t < KSTEPS * BATCH) ((unsigned long long*)g_slots)[t] = 0ull;
}

// Block-wide max of packed (value_bits<<32 | ~idx). Valid on thread 0.
__device__ __forceinline__ unsigned long long block_reduce_max(
        unsigned long long v, unsigned long long* sred) {
    #pragma unroll
    for (int s = 16; s > 0; s >>= 1) {
        unsigned long long o = __shfl_down_sync(0xFFFFFFFFu, v, s);
        if (o > v) v = o;
    }
    if ((threadIdx.x & 31) == 0) sred[threadIdx.x >> 5] = v;
    __syncthreads();
    if (threadIdx.x < 8) {
        v = sred[threadIdx.x];
        #pragma unroll
        for (int s = 4; s > 0; s >>= 1) {
            unsigned long long o = __shfl_down_sync(0x000000FFu, v, s);
            if (o > v) v = o;
        }
    }
    return v;
}

__device__ __forceinline__ unsigned long long pack_key(float key, int idx) {
    return ((unsigned long long)__float_as_uint(key) << 32)
         | (unsigned long long)(0xFFFFFFFFu - (unsigned)idx);
}

// Packed fp32x2 helpers (sm_103a packed-FMA pipe, rt=1 vs 2 for scalar FFMA)
__device__ __forceinline__ unsigned long long pack2(float lo, float hi) {
    unsigned long long r;
    asm("mov.b64 %0, {%1, %2};" : "=l"(r) : "f"(lo), "f"(hi));
    return r;
}
__device__ __forceinline__ void unpack2(float& lo, float& hi, unsigned long long v) {
    asm("mov.b64 {%0, %1}, %2;" : "=f"(lo), "=f"(hi) : "l"(v));
}
__device__ __forceinline__ void ffma2(unsigned long long& d,
                                      unsigned long long a, unsigned long long b) {
    asm("fma.rn.f32x2 %0, %1, %2, %0;" : "+l"(d) : "l"(a), "l"(b));
}

// -------------------------------------------------------------------------
// Kernel 0: feat = gate*(W@x + b) + coord grid; scopes[:,0]=1;
// partial argmax of rand into slot 0. Inner GEMM uses packed f32x2 FMA.
// Grid: 2048 blocks x 256 threads, 4 consecutive pixels/thread (x coalesced).
__global__ void __launch_bounds__(256) k_feat(
        const float* __restrict__ x, const float* __restrict__ rnd,
        const float* __restrict__ w, const float* __restrict__ bias,
        const float* __restrict__ gate_p, float* __restrict__ out) {
    __shared__ unsigned long long swp[CIN * COUT];   // duplicated packed weights [c][o]
    __shared__ float sb[COUT];
    __shared__ unsigned long long sred[8];
    int tid = threadIdx.x;
    for (int i = tid; i < CIN * COUT; i += 256) {
        int o = i / CIN, c = i % CIN;
        float wv = w[i];
        swp[c * COUT + o] = pack2(wv, wv);           // transposed + duplicated
    }
    if (tid < COUT) sb[tid] = bias[tid];
    __syncthreads();

    float gate = *gate_p;
    int b     = blockIdx.x >> 6;
    int pin   = (blockIdx.x & 63) * 1024 + tid * 4;   // pixel-in-batch
    const float4* x4 = (const float4*)x + ((size_t)b * CIN) * (HW / 4) + (pin >> 2);

    unsigned long long acc[COUT][2];                  // pairs: px{0,1}, px{2,3}
    #pragma unroll
    for (int o = 0; o < COUT; o++) {
        float bv = sb[o];
        acc[o][0] = pack2(bv, bv);
        acc[o][1] = pack2(bv, bv);
    }

    #pragma unroll 8
    for (int c = 0; c < CIN; c++) {
        float4 v = __ldcs(&x4[(size_t)c * (HW / 4)]);   // x never re-read: stream
        unsigned long long xp0 = pack2(v.x, v.y);
        unsigned long long xp1 = pack2(v.z, v.w);
        #pragma unroll
        for (int o = 0; o < COUT; o++) {
            unsigned long long wp = swp[c * COUT + o];
            ffma2(acc[o][0], wp, xp0);
            ffma2(acc[o][1], wp, xp1);
        }
    }

    float accf[COUT][4];
    #pragma unroll
    for (int o = 0; o < COUT; o++) {
        unpack2(accf[o][0], accf[o][1], acc[o][0]);
        unpack2(accf[o][2], accf[o][3], acc[o][1]);
    }

    const float step = 2.0f / 255.0f;
    #pragma unroll
    for (int j = 0; j < 4; j++) {
        int p  = pin + j;
        int h  = p >> 8;
        int wi = p & 255;
        float4 f0, f1;
        f0.x = gate * accf[0][j]; f0.y = gate * accf[1][j];
        f0.z = gate * accf[2][j]; f0.w = gate * accf[3][j];
        f1.x = gate * accf[4][j]; f1.y = gate * accf[5][j];
        f1.z = fmaf((float)h,  step, -1.0f) + gate * accf[6][j];
        f1.w = fmaf((float)wi, step, -1.0f) + gate * accf[7][j];
        size_t fb = (size_t)b * HW + p;
        g_feat0[fb] = f0;
        g_feat1[fb] = f1;
    }

    // scopes[b,0,:] = 1  (re-read by step 0)
    float4 ones = make_float4(1.0f, 1.0f, 1.0f, 1.0f);
    float* scopes = out + (size_t)BATCH * KSTEPS * HW;
    *(float4*)&scopes[((size_t)b * KSTEPS) * HW + pin] = ones;

    // argmax of rand (scope == 1) for step 0
    float4 rv = ((const float4*)rnd)[((size_t)b * HW + pin) >> 2];
    float rj[4] = {rv.x, rv.y, rv.z, rv.w};
    unsigned long long best = 0ull;
    #pragma unroll
    for (int j = 0; j < 4; j++) {
        unsigned long long pk = pack_key(rj[j], pin + j);
        if (pk > best) best = pk;
    }
    best = block_reduce_max(best, sred);
    if (tid == 0) atomicMax(&g_slots[0][b], best);
}

// -------------------------------------------------------------------------
// Step kernel k = 0..9: seed from slot[k]; alpha; write masks[:,k],
// scopes[:,k+1]; partial argmax into slot[k+1] (k==9 -> masks[:,10]=scope).
// Scope chain lives in the scopes output tensor itself (read slice k).
// All loads front-batched for MLP; coalesced mapping p = base + tid + 256*j.
__global__ void __launch_bounds__(256) k_step(
        const float* __restrict__ rnd, const float* __restrict__ lsig_p,
        float* __restrict__ out, int k) {
    __shared__ unsigned long long sred[8];
    int tid = threadIdx.x;
    int b   = blockIdx.x >> 6;
    int pin = (blockIdx.x & 63) * 1024 + tid;

    unsigned long long sl = g_slots[k][b];
    unsigned int idx = 0xFFFFFFFFu - (unsigned int)(sl & 0xFFFFFFFFull);
    size_t seedbase = (size_t)b * HW + idx;
    float4 s0 = g_feat0[seedbase];
    float4 s1 = g_feat1[seedbase];
    float neg_inv_sigma = -1.0f / expf(*lsig_p);

    float* masks  = out;
    float* scopes = out + (size_t)BATCH * KSTEPS * HW;
    const float* scope_in = scopes + ((size_t)b * KSTEPS + k)     * HW;
    float* scope_out = scopes + ((size_t)b * KSTEPS + k + 1) * HW;
    float* mask_out  = masks  + ((size_t)b * KSTEPS + k)     * HW;
    float* mask_last = masks  + ((size_t)b * KSTEPS + KSTEPS - 1) * HW;

    // ---- front-batched loads (16 LDG issued back-to-back) ----
    float  sj[4], rj[4];
    float4 f0v[4], f1v[4];
    #pragma unroll
    for (int j = 0; j < 4; j++) {
        int p = pin + 256 * j;
        size_t base = (size_t)b * HW + p;
        sj[j]  = scope_in[p];
        rj[j]  = rnd[base];
        f0v[j] = g_feat0[base];
        f1v[j] = g_feat1[base];
    }

    // ---- compute + store ----
    unsigned long long best = 0ull;
    #pragma unroll
    for (int j = 0; j < 4; j++) {
        int p = pin + 256 * j;
        float4 f0 = f0v[j], f1 = f1v[j];
        float d = 0.0f, t;
        t = f0.x - s0.x; d = fmaf(t, t, d);
        t = f0.y - s0.y; d = fmaf(t, t, d);
        t = f0.z - s0.z; d = fmaf(t, t, d);
        t = f0.w - s0.w; d = fmaf(t, t, d);
        t = f1.x - s1.x; d = fmaf(t, t, d);
        t = f1.y - s1.y; d = fmaf(t, t, d);
        t = f1.z - s1.z; d = fmaf(t, t, d);
        t = f1.w - s1.w; d = fmaf(t, t, d);
        float a = expf(d * neg_inv_sigma);
        a = fminf(fmaxf(a, 0.01f), 0.99f);
        float s  = sj[j];
        float m  = s * a;
        float ns = s * (1.0f - a);
        __stwt(&mask_out[p], m);            // never re-read
        scope_out[p] = ns;                  // re-read next step
        if (k == KSTEPS - 2) {
            __stwt(&mask_last[p], ns);      // masks[:,10] = final scope
        } else {
            unsigned long long pk = pack_key(rj[j] * ns, p);
            if (pk > best) best = pk;
        }
    }

    if (k != KSTEPS - 2) {
        best = block_reduce_max(best, sred);
        if (tid == 0) atomicMax(&g_slots[k + 1][b], best);
    }
}

// -------------------------------------------------------------------------
extern "C" void kernel_launch(void* const* d_in, const int* in_sizes, int n_in,
                              void* d_out, int out_size) {
    const float* x    = (const float*)d_in[0];
    const float* rnd  = (const float*)d_in[1];
    const float* w    = (const float*)d_in[2];
    const float* bias = (const float*)d_in[3];
    const float* gate = (const float*)d_in[4];
    const float* lsig = (const float*)d_in[5];
    float* out = (float*)d_out;

    k_init_slots<<<1, KSTEPS * BATCH>>>();
    k_feat<<<BATCH * 64, 256>>>(x, rnd, w, bias, gate, out);
    for (int k = 0; k < KSTEPS - 1; k++)
        k_step<<<BATCH * 64, 256>>>(rnd, lsig, out, k);
}